// round 1
// baseline (speedup 1.0000x reference)
#include <cuda_runtime.h>
#include <cstdint>

// Problem constants
#define NLEN   8192
#define LOGN   13
#define HALF_N (NLEN/2)
#define MODES  1024
#define BATCH  32
#define CIN    64
#define COUT   64
#define IROWS  (BATCH*CIN)    // 2048 input rows
#define OROWS  (BATCH*COUT)   // 2048 output rows

// -------- scratch (no allocations allowed; use __device__ globals) --------
__device__ float g_table[HALF_N];                 // cas(2*pi*t/8192)
__device__ float g_xm  [IROWS*MODES];             // [row=b*64+i][m]
__device__ float g_xmT [MODES*IROWS];             // [m][row]
__device__ float g_wT  [MODES*CIN*COUT];          // [m][i*64+o]
__device__ float g_zT  [MODES*OROWS];             // [m][b*64+o]
__device__ float g_z   [OROWS*MODES];             // [row=b*64+o][m]

// Bank-conflict-avoiding smem swizzle: XOR bits 8..12 into bits 0..4.
__device__ __forceinline__ int phi(int s)   { return s ^ ((s >> 8) & 31); }
__device__ __forceinline__ int rev13(int i) { return (int)(__brev((unsigned)i) >> 19); }

// ---------------------------------------------------------------------------
__global__ void init_table_kernel() {
    int t = blockIdx.x * blockDim.x + threadIdx.x;
    if (t < HALF_N) {
        // theta = 2*pi*t/8192 = pi * (t/4096)
        float s, c;
        sincospif((float)t * (1.0f / 4096.0f), &s, &c);
        g_table[t] = c + s;
    }
}

// Shared in-place cas-FHT stages. smem holds bit-reversed input under phi().
__device__ __forceinline__ void fht_stages(float* sm) {
    const int tid = threadIdx.x;
    #pragma unroll 1
    for (int j = 1; j <= LOGN; j++) {
        const int half   = 1 << (j - 1);
        const int tshift = LOGN - j;
        #pragma unroll
        for (int s = 0; s < NLEN / 1024; s++) {       // 4096 butterflies / 512 thr
            int b = s * 512 + tid;
            int k = b & (half - 1);
            int u = ((b >> (j - 1)) << j) + k;
            float cas = g_table[k << tshift];
            int pu = phi(u), pv = phi(u + half);
            float e = sm[pu];
            float o = sm[pv];
            float t = cas * o;
            sm[pu] = e + t;
            sm[pv] = e - t;
        }
        __syncthreads();
    }
}

// Forward: x[row][0..8192) -> xm[row][0..1024)
__global__ __launch_bounds__(512) void fht_fwd_kernel(const float* __restrict__ x) {
    __shared__ float sm[NLEN];
    const int row = blockIdx.x;
    const int tid = threadIdx.x;
    const float* xr = x + (size_t)row * NLEN;

    #pragma unroll
    for (int t = 0; t < NLEN / 512; t++) {
        int i = t * 512 + tid;
        sm[phi(rev13(i))] = xr[i];
    }
    __syncthreads();

    fht_stages(sm);

    float* xmr = g_xm + (size_t)row * MODES;
    #pragma unroll
    for (int t = 0; t < MODES / 512; t++) {
        int m = t * 512 + tid;
        xmr[m] = sm[phi(m)];           // output is in natural order
    }
}

// Inverse: z[row][0..1024) (zero-padded to 8192) -> out[row][0..8192) / 8192
__global__ __launch_bounds__(512) void fht_inv_kernel(float* __restrict__ out) {
    __shared__ float sm[NLEN];
    const int row = blockIdx.x;
    const int tid = threadIdx.x;

    #pragma unroll
    for (int t = 0; t < NLEN / 512; t++) sm[t * 512 + tid] = 0.0f;
    __syncthreads();

    const float* zr = g_z + (size_t)row * MODES;
    #pragma unroll
    for (int t = 0; t < MODES / 512; t++) {
        int m = t * 512 + tid;
        sm[phi(rev13(m))] = zr[m];
    }
    __syncthreads();

    fht_stages(sm);

    float* orow = out + (size_t)row * NLEN;
    const float scale = 1.0f / (float)NLEN;
    #pragma unroll
    for (int t = 0; t < NLEN / 512; t++) {
        int i = t * 512 + tid;
        orow[i] = sm[phi(i)] * scale;
    }
}

// Generic 32x32-tile transpose: src[R][C] -> dst[C][R]. R,C multiples of 32.
__global__ void transpose_kernel(const float* __restrict__ src,
                                 float* __restrict__ dst, int R, int C) {
    __shared__ float tile[32][33];
    int c0 = blockIdx.x * 32, r0 = blockIdx.y * 32;
    int tx = threadIdx.x, ty = threadIdx.y;
    #pragma unroll
    for (int dy = 0; dy < 32; dy += 8)
        tile[ty + dy][tx] = src[(size_t)(r0 + ty + dy) * C + (c0 + tx)];
    __syncthreads();
    #pragma unroll
    for (int dy = 0; dy < 32; dy += 8)
        dst[(size_t)(c0 + ty + dy) * R + (r0 + tx)] = tile[tx][ty + dy];
}

// Mode mixing. One block per mode m; pairs with m' = (1024-m) mod 1024.
// z(m)[b][o] = sum_i ( a[b][i]*w_m[i][o] + d[b][i]*w_m'[i][o] )
// where a = 0.5*(x(m)+x(m')), d = 0.5*(x(m)-x(m')).
__global__ __launch_bounds__(256) void mix_kernel() {
    __shared__ float sa[IROWS];          // [b*64+i]
    __shared__ float sd[IROWS];
    __shared__ float w0[CIN * COUT];     // w(m)  [i*64+o]
    __shared__ float w1[CIN * COUT];     // w(m') [i*64+o]

    const int m  = blockIdx.x;
    const int mp = (MODES - m) & (MODES - 1);
    const int tid = threadIdx.x;

    const float* xm0 = g_xmT + (size_t)m  * IROWS;
    const float* xm1 = g_xmT + (size_t)mp * IROWS;
    for (int t = tid; t < IROWS; t += 256) {
        float v0 = xm0[t], v1 = xm1[t];
        sa[t] = 0.5f * (v0 + v1);
        sd[t] = 0.5f * (v0 - v1);
    }
    const float* wm0 = g_wT + (size_t)m  * (CIN * COUT);
    const float* wm1 = g_wT + (size_t)mp * (CIN * COUT);
    for (int t = tid; t < CIN * COUT; t += 256) {
        w0[t] = wm0[t];
        w1[t] = wm1[t];
    }
    __syncthreads();

    // 256 threads, each computes a 2(b) x 4(o) tile -> 32 b x 64 o total
    const int b0 = (tid >> 4) * 2;
    const int o0 = (tid & 15) * 4;

    float acc00=0.f, acc01=0.f, acc02=0.f, acc03=0.f;
    float acc10=0.f, acc11=0.f, acc12=0.f, acc13=0.f;

    #pragma unroll 4
    for (int i = 0; i < CIN; i++) {
        float a0 = sa[b0 * CIN + i];
        float a1 = sa[(b0 + 1) * CIN + i];
        float d0 = sd[b0 * CIN + i];
        float d1 = sd[(b0 + 1) * CIN + i];
        float4 ww0 = *(const float4*)&w0[i * COUT + o0];
        float4 ww1 = *(const float4*)&w1[i * COUT + o0];
        acc00 += a0 * ww0.x + d0 * ww1.x;
        acc01 += a0 * ww0.y + d0 * ww1.y;
        acc02 += a0 * ww0.z + d0 * ww1.z;
        acc03 += a0 * ww0.w + d0 * ww1.w;
        acc10 += a1 * ww0.x + d1 * ww1.x;
        acc11 += a1 * ww0.y + d1 * ww1.y;
        acc12 += a1 * ww0.z + d1 * ww1.z;
        acc13 += a1 * ww0.w + d1 * ww1.w;
    }

    float* zr = g_zT + (size_t)m * OROWS;
    zr[b0 * COUT + o0 + 0] = acc00;
    zr[b0 * COUT + o0 + 1] = acc01;
    zr[b0 * COUT + o0 + 2] = acc02;
    zr[b0 * COUT + o0 + 3] = acc03;
    zr[(b0 + 1) * COUT + o0 + 0] = acc10;
    zr[(b0 + 1) * COUT + o0 + 1] = acc11;
    zr[(b0 + 1) * COUT + o0 + 2] = acc12;
    zr[(b0 + 1) * COUT + o0 + 3] = acc13;
}

// ---------------------------------------------------------------------------
extern "C" void kernel_launch(void* const* d_in, const int* in_sizes, int n_in,
                              void* d_out, int out_size) {
    const float* x = (const float*)d_in[0];   // [32][64][8192]
    const float* w = (const float*)d_in[1];   // [64][64][1024]
    float* out = (float*)d_out;               // [32][64][8192]

    float* xm  = nullptr; cudaGetSymbolAddress((void**)&xm,  g_xm);
    float* xmT = nullptr; cudaGetSymbolAddress((void**)&xmT, g_xmT);
    float* wT  = nullptr; cudaGetSymbolAddress((void**)&wT,  g_wT);
    float* zT  = nullptr; cudaGetSymbolAddress((void**)&zT,  g_zT);
    float* z   = nullptr; cudaGetSymbolAddress((void**)&z,   g_z);

    init_table_kernel<<<HALF_N / 512, 512>>>();

    fht_fwd_kernel<<<IROWS, 512>>>(x);

    // xm [2048][1024] -> xmT [1024][2048]
    transpose_kernel<<<dim3(MODES / 32, IROWS / 32), dim3(32, 8)>>>(xm, xmT, IROWS, MODES);
    // w  [4096][1024] -> wT  [1024][4096]
    transpose_kernel<<<dim3(MODES / 32, (CIN * COUT) / 32), dim3(32, 8)>>>(w, wT, CIN * COUT, MODES);

    mix_kernel<<<MODES, 256>>>();

    // zT [1024][2048] -> z [2048][1024]
    transpose_kernel<<<dim3(OROWS / 32, MODES / 32), dim3(32, 8)>>>(zT, z, MODES, OROWS);

    fht_inv_kernel<<<OROWS, 512>>>(out);
}

// round 2
// speedup vs baseline: 2.9513x; 2.9513x over previous
#include <cuda_runtime.h>
#include <cstdint>

// Problem constants
#define NLEN   8192
#define LOGN   13
#define HALF_N (NLEN/2)
#define MODES  1024
#define BATCH  32
#define CIN    64
#define COUT   64
#define IROWS  (BATCH*CIN)    // 2048 input rows
#define OROWS  (BATCH*COUT)   // 2048 output rows

// -------- scratch (no allocations allowed; use __device__ globals) --------
__device__ float g_table[HALF_N];                 // cas(2*pi*t/8192)
__device__ float g_xm  [IROWS*MODES];             // [row=b*64+i][m]
__device__ float g_xmT [MODES*IROWS];             // [m][row]
__device__ float g_wT  [MODES*CIN*COUT];          // [m][i*64+o]
__device__ float g_zT  [MODES*OROWS];             // [m][b*64+o]
__device__ float g_z   [OROWS*MODES];             // [row=b*64+o][m]

// GF(2)-linear smem swizzle: bank(u) bijective on lane-varying bit-groups
// {8..12} (bitrev scatter), {4..8} (phase A), {0..3,8} (phase B), {0..4} (phase C).
// k0..2 ^= u5..7 ^ u9..11 ; k3 ^= u8 ; k4 ^= u8 ^ u12.
__device__ __forceinline__ int swz(int u) {
    int f = ((u >> 5) & 7) ^ ((u >> 9) & 7)
          ^ (((u >> 8) & 1) * 0x18)
          ^ (((u >> 12) & 1) * 0x10);
    return u ^ f;
}

// ---------------------------------------------------------------------------
__global__ void init_table_kernel() {
    int t = blockIdx.x * blockDim.x + threadIdx.x;
    if (t < HALF_N) {
        float s, c;
        sincospif((float)t * (1.0f / 4096.0f), &s, &c);
        g_table[t] = c + s;
    }
}

// -------- shared phase bodies (fully unrolled; r[] stays in registers) ------

// Phase B: stages 5-8. Thread t owns u = (t>>4)<<8 | s<<4 | (t&15), s=0..15.
__device__ __forceinline__ void phaseB(float* sm, float r[16], int t,
                                       const float* __restrict__ tab) {
    const int lo = t & 15;
    const int base = ((t >> 4) << 8) | lo;
    #pragma unroll
    for (int s = 0; s < 16; s++) r[s] = sm[swz(base | (s << 4))];
    // stage 5: k = lo (one cas for all s)
    {
        float cas = tab[lo << 8];
        #pragma unroll
        for (int s = 0; s < 16; s += 2) {
            float o = cas * r[s + 1]; r[s + 1] = r[s] - o; r[s] += o;
        }
    }
    // stage 6: k = ((s&1)<<4)|lo
    #pragma unroll
    for (int sb = 0; sb < 2; sb++) {
        float cas = tab[((sb << 4) | lo) << 7];
        #pragma unroll
        for (int g = 0; g < 16; g += 4) {
            int s = g + sb;
            float o = cas * r[s + 2]; r[s + 2] = r[s] - o; r[s] += o;
        }
    }
    // stage 7: k = ((s&3)<<4)|lo
    #pragma unroll
    for (int sb = 0; sb < 4; sb++) {
        float cas = tab[((sb << 4) | lo) << 6];
        #pragma unroll
        for (int g = 0; g < 16; g += 8) {
            int s = g + sb;
            float o = cas * r[s + 4]; r[s + 4] = r[s] - o; r[s] += o;
        }
    }
    // stage 8: k = (s<<4)|lo, s<8
    #pragma unroll
    for (int s = 0; s < 8; s++) {
        float cas = tab[((s << 4) | lo) << 5];
        float o = cas * r[s + 8]; r[s + 8] = r[s] - o; r[s] += o;
    }
    #pragma unroll
    for (int s = 0; s < 16; s++) sm[swz(base | (s << 4))] = r[s];
}

// Phase C stages 9,10 (shared by fwd/inv). u = (t>>8)<<12 | s<<8 | (t&255).
__device__ __forceinline__ void phaseC_910(float r[16], int low8,
                                           const float* __restrict__ tab) {
    // stage 9: k = low8
    {
        float cas = tab[low8 << 4];
        #pragma unroll
        for (int s = 0; s < 16; s += 2) {
            float o = cas * r[s + 1]; r[s + 1] = r[s] - o; r[s] += o;
        }
    }
    // stage 10: k = ((s&1)<<8)|low8
    #pragma unroll
    for (int sb = 0; sb < 2; sb++) {
        float cas = tab[((sb << 8) | low8) << 3];
        #pragma unroll
        for (int g = 0; g < 16; g += 4) {
            int s = g + sb;
            float o = cas * r[s + 2]; r[s + 2] = r[s] - o; r[s] += o;
        }
    }
}

// -------- forward: x[row][0..8192) -> xm[row][0..1024) ----------------------
__global__ __launch_bounds__(512, 2) void fht_fwd_kernel(const float* __restrict__ x) {
    __shared__ float sm[NLEN];
    const int row = blockIdx.x;
    const int t = threadIdx.x;
    const float* __restrict__ xr = x + (size_t)row * NLEN;
    const float* __restrict__ tab = g_table;

    // bit-reversed scatter (coalesced global read, conflict-free smem write)
    #pragma unroll
    for (int q = 0; q < 16; q++) {
        int i = q * 512 + t;
        int u = (int)(__brev((unsigned)i) >> 19);
        sm[swz(u)] = xr[i];
    }
    __syncthreads();

    float r[16];

    // ---- Phase A: stages 1-4 on u = 16t+e
    {
        #pragma unroll
        for (int e = 0; e < 16; e++) r[e] = sm[swz(t * 16 + e)];
        // stage 1 (cas = 1)
        #pragma unroll
        for (int e = 0; e < 16; e += 2) {
            float o = r[e + 1]; r[e + 1] = r[e] - o; r[e] += o;
        }
        // stage 2 (cas(0)=cas(pi/2)=1)
        #pragma unroll
        for (int g = 0; g < 16; g += 4)
            #pragma unroll
            for (int e = g; e < g + 2; e++) {
                float o = r[e + 2]; r[e + 2] = r[e] - o; r[e] += o;
            }
        // stage 3: cas = tab[(e&3)<<10]
        #pragma unroll
        for (int eb = 0; eb < 4; eb++) {
            float cas = tab[eb << 10];
            #pragma unroll
            for (int g = 0; g < 16; g += 8) {
                int e = g + eb;
                float o = cas * r[e + 4]; r[e + 4] = r[e] - o; r[e] += o;
            }
        }
        // stage 4: cas = tab[e<<9]
        #pragma unroll
        for (int e = 0; e < 8; e++) {
            float cas = tab[e << 9];
            float o = cas * r[e + 8]; r[e + 8] = r[e] - o; r[e] += o;
        }
        #pragma unroll
        for (int e = 0; e < 16; e++) sm[swz(t * 16 + e)] = r[e];
    }
    __syncthreads();

    phaseB(sm, r, t, tab);
    __syncthreads();

    // ---- Phase C: stages 9-12, 11/12 pruned to '+' branch (modes<1024 only)
    {
        const int low8 = t & 255;
        const int base = ((t >> 8) << 12) | low8;
        #pragma unroll
        for (int s = 0; s < 16; s++) r[s] = sm[swz(base | (s << 8))];
        phaseC_910(r, low8, tab);
        // stage 11 pruned: keep s with bit10==0 -> s in {0..3, 8..11}
        #pragma unroll
        for (int sb = 0; sb < 4; sb++) {
            float cas = tab[((sb << 8) | low8) << 2];
            r[sb]     += cas * r[sb + 4];
            r[sb + 8] += cas * r[sb + 12];
        }
        // stage 12 pruned: keep s in {0..3}
        #pragma unroll
        for (int s = 0; s < 4; s++) {
            float cas = tab[((s << 8) | low8) << 1];
            r[s] += cas * r[s + 8];
        }
        #pragma unroll
        for (int s = 0; s < 4; s++) sm[swz(base | (s << 8))] = r[s];
    }
    __syncthreads();

    // ---- stage 13 pruned + output
    float* __restrict__ xmr = g_xm + (size_t)row * MODES;
    #pragma unroll
    for (int q = 0; q < 2; q++) {
        int m = q * 512 + t;
        float e = sm[swz(m)];
        float o = sm[swz(m + 4096)];
        xmr[m] = e + tab[m] * o;
    }
}

// -------- inverse: z[row][0..1024) zero-padded -> out[row][0..8192)/8192 ----
__global__ __launch_bounds__(512, 2) void fht_inv_kernel(float* __restrict__ out) {
    __shared__ float sm[NLEN];
    const int row = blockIdx.x;
    const int t = threadIdx.x;
    const float* __restrict__ tab = g_table;
    const float* __restrict__ zr = g_z + (size_t)row * MODES;

    float r[16];

    // ---- stages 1-3 are exact broadcasts (input nonzero only at u%8==0);
    //      stage 4 computed directly from the two nonzero values.
    {
        int r9 = (int)(__brev((unsigned)t) >> 23);     // rev9(t)
        float v0 = zr[r9];          // a[16t]   = z[rev9(t)]
        float v1 = zr[r9 + 512];    // a[16t+8] = z[rev9(t)+512]
        #pragma unroll
        for (int e = 0; e < 8; e++) {
            float o = tab[e << 9] * v1;
            r[e] = v0 + o;
            r[e + 8] = v0 - o;
        }
        #pragma unroll
        for (int e = 0; e < 16; e++) sm[swz(t * 16 + e)] = r[e];
    }
    __syncthreads();

    phaseB(sm, r, t, tab);
    __syncthreads();

    // ---- Phase C: stages 9-12 full
    {
        const int low8 = t & 255;
        const int base = ((t >> 8) << 12) | low8;
        #pragma unroll
        for (int s = 0; s < 16; s++) r[s] = sm[swz(base | (s << 8))];
        phaseC_910(r, low8, tab);
        // stage 11 full: pairs (s, s+4), s bit2 == 0
        #pragma unroll
        for (int sb = 0; sb < 4; sb++) {
            float cas = tab[((sb << 8) | low8) << 2];
            float o0 = cas * r[sb + 4];  r[sb + 4]  = r[sb]     - o0; r[sb]     += o0;
            float o1 = cas * r[sb + 12]; r[sb + 12] = r[sb + 8] - o1; r[sb + 8] += o1;
        }
        // stage 12 full: pairs (s, s+8), s<8
        #pragma unroll
        for (int s = 0; s < 8; s++) {
            float cas = tab[((s << 8) | low8) << 1];
            float o = cas * r[s + 8]; r[s + 8] = r[s] - o; r[s] += o;
        }
        #pragma unroll
        for (int s = 0; s < 16; s++) sm[swz(base | (s << 8))] = r[s];
    }
    __syncthreads();

    // ---- stage 13 fused with scaled coalesced store
    const float scale = 1.0f / (float)NLEN;
    float* __restrict__ orow = out + (size_t)row * NLEN;
    #pragma unroll
    for (int q = 0; q < 8; q++) {
        int k = q * 512 + t;
        float e = sm[swz(k)];
        float o = sm[swz(k + 4096)];
        float tt = tab[k] * o;
        orow[k] = (e + tt) * scale;
        orow[k + 4096] = (e - tt) * scale;
    }
}

// -------- generic 32x32 transpose ------------------------------------------
__global__ void transpose_kernel(const float* __restrict__ src,
                                 float* __restrict__ dst, int R, int C) {
    __shared__ float tile[32][33];
    int c0 = blockIdx.x * 32, r0 = blockIdx.y * 32;
    int tx = threadIdx.x, ty = threadIdx.y;
    #pragma unroll
    for (int dy = 0; dy < 32; dy += 8)
        tile[ty + dy][tx] = src[(size_t)(r0 + ty + dy) * C + (c0 + tx)];
    __syncthreads();
    #pragma unroll
    for (int dy = 0; dy < 32; dy += 8)
        dst[(size_t)(c0 + ty + dy) * R + (r0 + tx)] = tile[tx][ty + dy];
}

// -------- paired mode mixing: block m computes z(m) AND z(m') ---------------
// z(m)  = sum_i a*w(m)  + d*w(m')
// z(m') = sum_i a*w(m') - d*w(m)      (a = (x(m)+x(m'))/2, d = (x(m)-x(m'))/2)
__global__ __launch_bounds__(256) void mix_kernel() {
    __shared__ float sa[IROWS];
    __shared__ float sd[IROWS];
    __shared__ float w0[CIN * COUT];
    __shared__ float w1[CIN * COUT];

    const int m  = blockIdx.x;                 // 0..512
    const int mp = (MODES - m) & (MODES - 1);
    const int tid = threadIdx.x;

    const float* xm0 = g_xmT + (size_t)m  * IROWS;
    const float* xm1 = g_xmT + (size_t)mp * IROWS;
    for (int t = tid; t < IROWS; t += 256) {
        float v0 = xm0[t], v1 = xm1[t];
        sa[t] = 0.5f * (v0 + v1);
        sd[t] = 0.5f * (v0 - v1);
    }
    const float* wm0 = g_wT + (size_t)m  * (CIN * COUT);
    const float* wm1 = g_wT + (size_t)mp * (CIN * COUT);
    for (int t = tid; t < CIN * COUT; t += 256) {
        w0[t] = wm0[t];
        w1[t] = wm1[t];
    }
    __syncthreads();

    const int b0 = (tid >> 4) * 2;
    const int o0 = (tid & 15) * 4;

    float A00=0.f,A01=0.f,A02=0.f,A03=0.f, A10=0.f,A11=0.f,A12=0.f,A13=0.f;
    float B00=0.f,B01=0.f,B02=0.f,B03=0.f, B10=0.f,B11=0.f,B12=0.f,B13=0.f;

    #pragma unroll 4
    for (int i = 0; i < CIN; i++) {
        float a0 = sa[b0 * CIN + i];
        float a1 = sa[(b0 + 1) * CIN + i];
        float d0 = sd[b0 * CIN + i];
        float d1 = sd[(b0 + 1) * CIN + i];
        float4 ww0 = *(const float4*)&w0[i * COUT + o0];
        float4 ww1 = *(const float4*)&w1[i * COUT + o0];
        A00 += a0*ww0.x + d0*ww1.x;  A01 += a0*ww0.y + d0*ww1.y;
        A02 += a0*ww0.z + d0*ww1.z;  A03 += a0*ww0.w + d0*ww1.w;
        A10 += a1*ww0.x + d1*ww1.x;  A11 += a1*ww0.y + d1*ww1.y;
        A12 += a1*ww0.z + d1*ww1.z;  A13 += a1*ww0.w + d1*ww1.w;
        B00 += a0*ww1.x - d0*ww0.x;  B01 += a0*ww1.y - d0*ww0.y;
        B02 += a0*ww1.z - d0*ww0.z;  B03 += a0*ww1.w - d0*ww0.w;
        B10 += a1*ww1.x - d1*ww0.x;  B11 += a1*ww1.y - d1*ww0.y;
        B12 += a1*ww1.z - d1*ww0.z;  B13 += a1*ww1.w - d1*ww0.w;
    }

    float* zr = g_zT + (size_t)m * OROWS;
    zr[b0*COUT + o0 + 0] = A00; zr[b0*COUT + o0 + 1] = A01;
    zr[b0*COUT + o0 + 2] = A02; zr[b0*COUT + o0 + 3] = A03;
    zr[(b0+1)*COUT + o0 + 0] = A10; zr[(b0+1)*COUT + o0 + 1] = A11;
    zr[(b0+1)*COUT + o0 + 2] = A12; zr[(b0+1)*COUT + o0 + 3] = A13;

    if (mp != m) {
        float* zp = g_zT + (size_t)mp * OROWS;
        zp[b0*COUT + o0 + 0] = B00; zp[b0*COUT + o0 + 1] = B01;
        zp[b0*COUT + o0 + 2] = B02; zp[b0*COUT + o0 + 3] = B03;
        zp[(b0+1)*COUT + o0 + 0] = B10; zp[(b0+1)*COUT + o0 + 1] = B11;
        zp[(b0+1)*COUT + o0 + 2] = B12; zp[(b0+1)*COUT + o0 + 3] = B13;
    }
}

// ---------------------------------------------------------------------------
extern "C" void kernel_launch(void* const* d_in, const int* in_sizes, int n_in,
                              void* d_out, int out_size) {
    const float* x = (const float*)d_in[0];   // [32][64][8192]
    const float* w = (const float*)d_in[1];   // [64][64][1024]
    float* out = (float*)d_out;               // [32][64][8192]

    float* xm  = nullptr; cudaGetSymbolAddress((void**)&xm,  g_xm);
    float* xmT = nullptr; cudaGetSymbolAddress((void**)&xmT, g_xmT);
    float* wT  = nullptr; cudaGetSymbolAddress((void**)&wT,  g_wT);
    float* zT  = nullptr; cudaGetSymbolAddress((void**)&zT,  g_zT);
    float* z   = nullptr; cudaGetSymbolAddress((void**)&z,   g_z);

    init_table_kernel<<<HALF_N / 512, 512>>>();

    fht_fwd_kernel<<<IROWS, 512>>>(x);

    // xm [2048][1024] -> xmT [1024][2048]
    transpose_kernel<<<dim3(MODES / 32, IROWS / 32), dim3(32, 8)>>>(xm, xmT, IROWS, MODES);
    // w  [4096][1024] -> wT  [1024][4096]
    transpose_kernel<<<dim3(MODES / 32, (CIN * COUT) / 32), dim3(32, 8)>>>(w, wT, CIN * COUT, MODES);

    mix_kernel<<<MODES / 2 + 1, 256>>>();     // 513 blocks: m and m' paired

    // zT [1024][2048] -> z [2048][1024]
    transpose_kernel<<<dim3(OROWS / 32, MODES / 32), dim3(32, 8)>>>(zT, z, MODES, OROWS);

    fht_inv_kernel<<<OROWS, 512>>>(out);
}

// round 3
// speedup vs baseline: 2.9518x; 1.0002x over previous
#include <cuda_runtime.h>
#include <cstdint>

// Problem constants
#define NLEN   8192
#define LOGN   13
#define HALF_N (NLEN/2)
#define MODES  1024
#define BATCH  32
#define CIN    64
#define COUT   64
#define IROWS  (BATCH*CIN)    // 2048 input rows
#define OROWS  (BATCH*COUT)   // 2048 output rows

// -------- scratch (no allocations allowed; use __device__ globals) --------
__device__ float g_table[HALF_N];                 // cas(2*pi*t/8192)
__device__ float g_xm  [IROWS*MODES];             // [row=b*64+i][m]
__device__ float g_xmT [MODES*IROWS];             // [m][row]
__device__ float g_wT  [MODES*CIN*COUT];          // [m][i*64+o]
__device__ float g_zT  [MODES*OROWS];             // [m][b*64+o]
__device__ float g_z   [OROWS*MODES];             // [row=b*64+o][m]

// GF(2)-linear smem swizzle: bank(u) bijective on lane-varying bit-groups
// {8..12} (bitrev scatter), {4..8} (phase A), {0..3,8} (phase B), {0..4} (phase C).
// k0..2 ^= u5..7 ^ u9..11 ; k3 ^= u8 ; k4 ^= u8 ^ u12.
__device__ __forceinline__ int swz(int u) {
    int f = ((u >> 5) & 7) ^ ((u >> 9) & 7)
          ^ (((u >> 8) & 1) * 0x18)
          ^ (((u >> 12) & 1) * 0x10);
    return u ^ f;
}

// ---------------------------------------------------------------------------
__global__ void init_table_kernel() {
    int t = blockIdx.x * blockDim.x + threadIdx.x;
    if (t < HALF_N) {
        float s, c;
        sincospif((float)t * (1.0f / 4096.0f), &s, &c);
        g_table[t] = c + s;
    }
}

// -------- shared phase bodies (fully unrolled; r[] stays in registers) ------

// Phase B: stages 5-8. Thread t owns u = (t>>4)<<8 | s<<4 | (t&15), s=0..15.
__device__ __forceinline__ void phaseB(float* sm, float r[16], int t,
                                       const float* __restrict__ tab) {
    const int lo = t & 15;
    const int base = ((t >> 4) << 8) | lo;
    #pragma unroll
    for (int s = 0; s < 16; s++) r[s] = sm[swz(base | (s << 4))];
    // stage 5: k = lo (one cas for all s)
    {
        float cas = tab[lo << 8];
        #pragma unroll
        for (int s = 0; s < 16; s += 2) {
            float o = cas * r[s + 1]; r[s + 1] = r[s] - o; r[s] += o;
        }
    }
    // stage 6: k = ((s&1)<<4)|lo
    #pragma unroll
    for (int sb = 0; sb < 2; sb++) {
        float cas = tab[((sb << 4) | lo) << 7];
        #pragma unroll
        for (int g = 0; g < 16; g += 4) {
            int s = g + sb;
            float o = cas * r[s + 2]; r[s + 2] = r[s] - o; r[s] += o;
        }
    }
    // stage 7: k = ((s&3)<<4)|lo
    #pragma unroll
    for (int sb = 0; sb < 4; sb++) {
        float cas = tab[((sb << 4) | lo) << 6];
        #pragma unroll
        for (int g = 0; g < 16; g += 8) {
            int s = g + sb;
            float o = cas * r[s + 4]; r[s + 4] = r[s] - o; r[s] += o;
        }
    }
    // stage 8: k = (s<<4)|lo, s<8
    #pragma unroll
    for (int s = 0; s < 8; s++) {
        float cas = tab[((s << 4) | lo) << 5];
        float o = cas * r[s + 8]; r[s + 8] = r[s] - o; r[s] += o;
    }
    #pragma unroll
    for (int s = 0; s < 16; s++) sm[swz(base | (s << 4))] = r[s];
}

// Phase C stages 9,10 (shared by fwd/inv). u = (t>>8)<<12 | s<<8 | (t&255).
__device__ __forceinline__ void phaseC_910(float r[16], int low8,
                                           const float* __restrict__ tab) {
    // stage 9: k = low8
    {
        float cas = tab[low8 << 4];
        #pragma unroll
        for (int s = 0; s < 16; s += 2) {
            float o = cas * r[s + 1]; r[s + 1] = r[s] - o; r[s] += o;
        }
    }
    // stage 10: k = ((s&1)<<8)|low8
    #pragma unroll
    for (int sb = 0; sb < 2; sb++) {
        float cas = tab[((sb << 8) | low8) << 3];
        #pragma unroll
        for (int g = 0; g < 16; g += 4) {
            int s = g + sb;
            float o = cas * r[s + 2]; r[s + 2] = r[s] - o; r[s] += o;
        }
    }
}

// -------- forward: x[row][0..8192) -> xm[row][0..1024) ----------------------
__global__ __launch_bounds__(512, 2) void fht_fwd_kernel(const float* __restrict__ x) {
    __shared__ float sm[NLEN];
    const int row = blockIdx.x;
    const int t = threadIdx.x;
    const float* __restrict__ xr = x + (size_t)row * NLEN;
    const float* __restrict__ tab = g_table;

    // bit-reversed scatter (coalesced global read, conflict-free smem write)
    #pragma unroll
    for (int q = 0; q < 16; q++) {
        int i = q * 512 + t;
        int u = (int)(__brev((unsigned)i) >> 19);
        sm[swz(u)] = xr[i];
    }
    __syncthreads();

    float r[16];

    // ---- Phase A: stages 1-4 on u = 16t+e
    {
        #pragma unroll
        for (int e = 0; e < 16; e++) r[e] = sm[swz(t * 16 + e)];
        // stage 1 (cas = 1)
        #pragma unroll
        for (int e = 0; e < 16; e += 2) {
            float o = r[e + 1]; r[e + 1] = r[e] - o; r[e] += o;
        }
        // stage 2 (cas(0)=cas(pi/2)=1)
        #pragma unroll
        for (int g = 0; g < 16; g += 4)
            #pragma unroll
            for (int e = g; e < g + 2; e++) {
                float o = r[e + 2]; r[e + 2] = r[e] - o; r[e] += o;
            }
        // stage 3: cas = tab[(e&3)<<10]
        #pragma unroll
        for (int eb = 0; eb < 4; eb++) {
            float cas = tab[eb << 10];
            #pragma unroll
            for (int g = 0; g < 16; g += 8) {
                int e = g + eb;
                float o = cas * r[e + 4]; r[e + 4] = r[e] - o; r[e] += o;
            }
        }
        // stage 4: cas = tab[e<<9]
        #pragma unroll
        for (int e = 0; e < 8; e++) {
            float cas = tab[e << 9];
            float o = cas * r[e + 8]; r[e + 8] = r[e] - o; r[e] += o;
        }
        #pragma unroll
        for (int e = 0; e < 16; e++) sm[swz(t * 16 + e)] = r[e];
    }
    __syncthreads();

    phaseB(sm, r, t, tab);
    __syncthreads();

    // ---- Phase C: stages 9-12, 11/12 pruned to '+' branch (modes<1024 only)
    {
        const int low8 = t & 255;
        const int base = ((t >> 8) << 12) | low8;
        #pragma unroll
        for (int s = 0; s < 16; s++) r[s] = sm[swz(base | (s << 8))];
        phaseC_910(r, low8, tab);
        // stage 11 pruned: keep s with bit10==0 -> s in {0..3, 8..11}
        #pragma unroll
        for (int sb = 0; sb < 4; sb++) {
            float cas = tab[((sb << 8) | low8) << 2];
            r[sb]     += cas * r[sb + 4];
            r[sb + 8] += cas * r[sb + 12];
        }
        // stage 12 pruned: keep s in {0..3}
        #pragma unroll
        for (int s = 0; s < 4; s++) {
            float cas = tab[((s << 8) | low8) << 1];
            r[s] += cas * r[s + 8];
        }
        #pragma unroll
        for (int s = 0; s < 4; s++) sm[swz(base | (s << 8))] = r[s];
    }
    __syncthreads();

    // ---- stage 13 pruned + output
    float* __restrict__ xmr = g_xm + (size_t)row * MODES;
    #pragma unroll
    for (int q = 0; q < 2; q++) {
        int m = q * 512 + t;
        float e = sm[swz(m)];
        float o = sm[swz(m + 4096)];
        xmr[m] = e + tab[m] * o;
    }
}

// -------- inverse: z[row][0..1024) zero-padded -> out[row][0..8192)/8192 ----
__global__ __launch_bounds__(512, 2) void fht_inv_kernel(float* __restrict__ out) {
    __shared__ float sm[NLEN];
    const int row = blockIdx.x;
    const int t = threadIdx.x;
    const float* __restrict__ tab = g_table;
    const float* __restrict__ zr = g_z + (size_t)row * MODES;

    float r[16];

    // ---- stages 1-3 are exact broadcasts (input nonzero only at u%8==0);
    //      stage 4 computed directly from the two nonzero values.
    {
        int r9 = (int)(__brev((unsigned)t) >> 23);     // rev9(t)
        float v0 = zr[r9];          // a[16t]   = z[rev9(t)]
        float v1 = zr[r9 + 512];    // a[16t+8] = z[rev9(t)+512]
        #pragma unroll
        for (int e = 0; e < 8; e++) {
            float o = tab[e << 9] * v1;
            r[e] = v0 + o;
            r[e + 8] = v0 - o;
        }
        #pragma unroll
        for (int e = 0; e < 16; e++) sm[swz(t * 16 + e)] = r[e];
    }
    __syncthreads();

    phaseB(sm, r, t, tab);
    __syncthreads();

    // ---- Phase C: stages 9-12 full
    {
        const int low8 = t & 255;
        const int base = ((t >> 8) << 12) | low8;
        #pragma unroll
        for (int s = 0; s < 16; s++) r[s] = sm[swz(base | (s << 8))];
        phaseC_910(r, low8, tab);
        // stage 11 full: pairs (s, s+4), s bit2 == 0
        #pragma unroll
        for (int sb = 0; sb < 4; sb++) {
            float cas = tab[((sb << 8) | low8) << 2];
            float o0 = cas * r[sb + 4];  r[sb + 4]  = r[sb]     - o0; r[sb]     += o0;
            float o1 = cas * r[sb + 12]; r[sb + 12] = r[sb + 8] - o1; r[sb + 8] += o1;
        }
        // stage 12 full: pairs (s, s+8), s<8
        #pragma unroll
        for (int s = 0; s < 8; s++) {
            float cas = tab[((s << 8) | low8) << 1];
            float o = cas * r[s + 8]; r[s + 8] = r[s] - o; r[s] += o;
        }
        #pragma unroll
        for (int s = 0; s < 16; s++) sm[swz(base | (s << 8))] = r[s];
    }
    __syncthreads();

    // ---- stage 13 fused with scaled coalesced store
    const float scale = 1.0f / (float)NLEN;
    float* __restrict__ orow = out + (size_t)row * NLEN;
    #pragma unroll
    for (int q = 0; q < 8; q++) {
        int k = q * 512 + t;
        float e = sm[swz(k)];
        float o = sm[swz(k + 4096)];
        float tt = tab[k] * o;
        orow[k] = (e + tt) * scale;
        orow[k + 4096] = (e - tt) * scale;
    }
}

// -------- generic 32x32 transpose ------------------------------------------
__global__ void transpose_kernel(const float* __restrict__ src,
                                 float* __restrict__ dst, int R, int C) {
    __shared__ float tile[32][33];
    int c0 = blockIdx.x * 32, r0 = blockIdx.y * 32;
    int tx = threadIdx.x, ty = threadIdx.y;
    #pragma unroll
    for (int dy = 0; dy < 32; dy += 8)
        tile[ty + dy][tx] = src[(size_t)(r0 + ty + dy) * C + (c0 + tx)];
    __syncthreads();
    #pragma unroll
    for (int dy = 0; dy < 32; dy += 8)
        dst[(size_t)(c0 + ty + dy) * R + (r0 + tx)] = tile[tx][ty + dy];
}

// -------- paired mode mixing: block m computes z(m) AND z(m') ---------------
// z(m)  = sum_i a*w(m)  + d*w(m')
// z(m') = sum_i a*w(m') - d*w(m)      (a = (x(m)+x(m'))/2, d = (x(m)-x(m'))/2)
__global__ __launch_bounds__(256) void mix_kernel() {
    __shared__ float sa[IROWS];
    __shared__ float sd[IROWS];
    __shared__ float w0[CIN * COUT];
    __shared__ float w1[CIN * COUT];

    const int m  = blockIdx.x;                 // 0..512
    const int mp = (MODES - m) & (MODES - 1);
    const int tid = threadIdx.x;

    const float* xm0 = g_xmT + (size_t)m  * IROWS;
    const float* xm1 = g_xmT + (size_t)mp * IROWS;
    for (int t = tid; t < IROWS; t += 256) {
        float v0 = xm0[t], v1 = xm1[t];
        sa[t] = 0.5f * (v0 + v1);
        sd[t] = 0.5f * (v0 - v1);
    }
    const float* wm0 = g_wT + (size_t)m  * (CIN * COUT);
    const float* wm1 = g_wT + (size_t)mp * (CIN * COUT);
    for (int t = tid; t < CIN * COUT; t += 256) {
        w0[t] = wm0[t];
        w1[t] = wm1[t];
    }
    __syncthreads();

    const int b0 = (tid >> 4) * 2;
    const int o0 = (tid & 15) * 4;

    float A00=0.f,A01=0.f,A02=0.f,A03=0.f, A10=0.f,A11=0.f,A12=0.f,A13=0.f;
    float B00=0.f,B01=0.f,B02=0.f,B03=0.f, B10=0.f,B11=0.f,B12=0.f,B13=0.f;

    #pragma unroll 4
    for (int i = 0; i < CIN; i++) {
        float a0 = sa[b0 * CIN + i];
        float a1 = sa[(b0 + 1) * CIN + i];
        float d0 = sd[b0 * CIN + i];
        float d1 = sd[(b0 + 1) * CIN + i];
        float4 ww0 = *(const float4*)&w0[i * COUT + o0];
        float4 ww1 = *(const float4*)&w1[i * COUT + o0];
        A00 += a0*ww0.x + d0*ww1.x;  A01 += a0*ww0.y + d0*ww1.y;
        A02 += a0*ww0.z + d0*ww1.z;  A03 += a0*ww0.w + d0*ww1.w;
        A10 += a1*ww0.x + d1*ww1.x;  A11 += a1*ww0.y + d1*ww1.y;
        A12 += a1*ww0.z + d1*ww1.z;  A13 += a1*ww0.w + d1*ww1.w;
        B00 += a0*ww1.x - d0*ww0.x;  B01 += a0*ww1.y - d0*ww0.y;
        B02 += a0*ww1.z - d0*ww0.z;  B03 += a0*ww1.w - d0*ww0.w;
        B10 += a1*ww1.x - d1*ww0.x;  B11 += a1*ww1.y - d1*ww0.y;
        B12 += a1*ww1.z - d1*ww0.z;  B13 += a1*ww1.w - d1*ww0.w;
    }

    float* zr = g_zT + (size_t)m * OROWS;
    zr[b0*COUT + o0 + 0] = A00; zr[b0*COUT + o0 + 1] = A01;
    zr[b0*COUT + o0 + 2] = A02; zr[b0*COUT + o0 + 3] = A03;
    zr[(b0+1)*COUT + o0 + 0] = A10; zr[(b0+1)*COUT + o0 + 1] = A11;
    zr[(b0+1)*COUT + o0 + 2] = A12; zr[(b0+1)*COUT + o0 + 3] = A13;

    if (mp != m) {
        float* zp = g_zT + (size_t)mp * OROWS;
        zp[b0*COUT + o0 + 0] = B00; zp[b0*COUT + o0 + 1] = B01;
        zp[b0*COUT + o0 + 2] = B02; zp[b0*COUT + o0 + 3] = B03;
        zp[(b0+1)*COUT + o0 + 0] = B10; zp[(b0+1)*COUT + o0 + 1] = B11;
        zp[(b0+1)*COUT + o0 + 2] = B12; zp[(b0+1)*COUT + o0 + 3] = B13;
    }
}

// ---------------------------------------------------------------------------
extern "C" void kernel_launch(void* const* d_in, const int* in_sizes, int n_in,
                              void* d_out, int out_size) {
    const float* x = (const float*)d_in[0];   // [32][64][8192]
    const float* w = (const float*)d_in[1];   // [64][64][1024]
    float* out = (float*)d_out;               // [32][64][8192]

    float* xm  = nullptr; cudaGetSymbolAddress((void**)&xm,  g_xm);
    float* xmT = nullptr; cudaGetSymbolAddress((void**)&xmT, g_xmT);
    float* wT  = nullptr; cudaGetSymbolAddress((void**)&wT,  g_wT);
    float* zT  = nullptr; cudaGetSymbolAddress((void**)&zT,  g_zT);
    float* z   = nullptr; cudaGetSymbolAddress((void**)&z,   g_z);

    init_table_kernel<<<HALF_N / 512, 512>>>();

    fht_fwd_kernel<<<IROWS, 512>>>(x);

    // xm [2048][1024] -> xmT [1024][2048]
    transpose_kernel<<<dim3(MODES / 32, IROWS / 32), dim3(32, 8)>>>(xm, xmT, IROWS, MODES);
    // w  [4096][1024] -> wT  [1024][4096]
    transpose_kernel<<<dim3(MODES / 32, (CIN * COUT) / 32), dim3(32, 8)>>>(w, wT, CIN * COUT, MODES);

    mix_kernel<<<MODES / 2 + 1, 256>>>();     // 513 blocks: m and m' paired

    // zT [1024][2048] -> z [2048][1024]
    transpose_kernel<<<dim3(OROWS / 32, MODES / 32), dim3(32, 8)>>>(zT, z, MODES, OROWS);

    fht_inv_kernel<<<OROWS, 512>>>(out);
}

// round 4
// speedup vs baseline: 3.9949x; 1.3534x over previous
#include <cuda_runtime.h>
#include <cstdint>

// Problem constants
#define NLEN   8192
#define LOGN   13
#define MODES  1024
#define BATCH  32
#define CIN    64
#define COUT   64
#define IROWS  (BATCH*CIN)    // 2048 input rows
#define OROWS  (BATCH*COUT)   // 2048 output rows

// -------- scratch (no allocations allowed; use __device__ globals) --------
// cas table extended to [0, 8192]: tab[k] = cas(2*pi*k/8192); tab[8192-k] = cas(-2*pi*k/8192)
__device__ __align__(32) float g_tab[8200];
__device__ float g_xm  [IROWS*MODES];             // [row=b*64+i][m]
__device__ float g_xmT [MODES*IROWS];             // [m][row]
__device__ float g_wT  [MODES*CIN*COUT];          // [m][i*64+o]
__device__ float g_zT  [MODES*OROWS];             // [m][b*64+o]
__device__ float g_z   [OROWS*MODES];             // [row=b*64+o][m]

// GF(2)-linear smem swizzle. k0^=u5^u9, k1^=u6^u10, k2^=u7^u11, k3^=u8, k4^=u8^u12.
__device__ __forceinline__ int swz(int u) {
    int f = ((u >> 5) & 7) ^ ((u >> 9) & 7)
          ^ (((u >> 8) & 1) * 0x18)
          ^ (((u >> 12) & 1) * 0x10);
    return u ^ f;
}
__device__ __forceinline__ int rev9(int t) { return (int)(__brev((unsigned)t) >> 23); }

// Literal cas values
#define RSQ2  0.70710678118654752f
#define C8L   0.92387953251128674f
#define S8L   0.38268343236508977f

// ---------------------------------------------------------------------------
__global__ void init_table_kernel() {
    int t = blockIdx.x * blockDim.x + threadIdx.x;
    if (t <= NLEN) {
        float s, c;
        sincospif((float)t * (1.0f / 4096.0f), &s, &c);
        g_tab[t] = c + s;
    }
}

// -------- Phase A stages 1-4: all twiddles are literals ---------------------
__device__ __forceinline__ void stagesA(float r[16]) {
    // stage 1 (cas=1)
    #pragma unroll
    for (int e = 0; e < 16; e += 2) {
        float o = r[e + 1]; r[e + 1] = r[e] - o; r[e] += o;
    }
    // stage 2 (cas(0)=cas(pi/2)=1)
    #pragma unroll
    for (int g = 0; g < 16; g += 4)
        #pragma unroll
        for (int e = g; e < g + 2; e++) {
            float o = r[e + 2]; r[e + 2] = r[e] - o; r[e] += o;
        }
    // stage 3: cas(eb*pi/4) = {1, sqrt2, 1, 0}
    {
        const float c3[4] = {1.0f, 1.41421356237309515f, 1.0f, 0.0f};
        #pragma unroll
        for (int eb = 0; eb < 4; eb++)
            #pragma unroll
            for (int g = 0; g < 16; g += 8) {
                int e = g + eb;
                float o = c3[eb] * r[e + 4]; r[e + 4] = r[e] - o; r[e] += o;
            }
    }
    // stage 4: cas(e*pi/8)
    {
        const float c4[8] = {1.0f, 1.30656296487637653f, 1.41421356237309515f,
                             1.30656296487637653f, 1.0f, 0.54119610014619701f,
                             0.0f, -0.54119610014619701f};
        #pragma unroll
        for (int e = 0; e < 8; e++) {
            float o = c4[e] * r[e + 8]; r[e + 8] = r[e] - o; r[e] += o;
        }
    }
}

// -------- Phase B stages 5-8: remapped so twiddles are warp-uniform ---------
// u = lane<<8 | s<<4 | wid  (lane = t&31, wid = t>>5). Twiddle k = (s<<4)|wid.
__device__ __forceinline__ void phaseB(float* sm, float r[16], int t,
                                       const float* __restrict__ tab) {
    const int wid  = t >> 5;
    const int lane = t & 31;
    const int base = (lane << 8) | wid;
    #pragma unroll
    for (int s = 0; s < 16; s++) r[s] = sm[swz(base | (s << 4))];
    // stage 5: k = wid
    {
        float cas = tab[wid << 8];
        #pragma unroll
        for (int s = 0; s < 16; s += 2) {
            float o = cas * r[s + 1]; r[s + 1] = r[s] - o; r[s] += o;
        }
    }
    // stage 6: k = ((s&1)<<4)|wid
    #pragma unroll
    for (int sb = 0; sb < 2; sb++) {
        float cas = tab[((sb << 4) | wid) << 7];
        #pragma unroll
        for (int g = 0; g < 16; g += 4) {
            int s = g + sb;
            float o = cas * r[s + 2]; r[s + 2] = r[s] - o; r[s] += o;
        }
    }
    // stage 7: k = ((s&3)<<4)|wid
    #pragma unroll
    for (int sb = 0; sb < 4; sb++) {
        float cas = tab[((sb << 4) | wid) << 6];
        #pragma unroll
        for (int g = 0; g < 16; g += 8) {
            int s = g + sb;
            float o = cas * r[s + 4]; r[s + 4] = r[s] - o; r[s] += o;
        }
    }
    // stage 8: k = (s<<4)|wid, s<8
    #pragma unroll
    for (int s = 0; s < 8; s++) {
        float cas = tab[((s << 4) | wid) << 5];
        float o = cas * r[s + 8]; r[s + 8] = r[s] - o; r[s] += o;
    }
    #pragma unroll
    for (int s = 0; s < 16; s++) sm[swz(base | (s << 4))] = r[s];
}

// -------- forward: x[row][0..8192) -> xm[row][0..1024) ----------------------
__global__ __launch_bounds__(512, 2) void fht_fwd_kernel(const float* __restrict__ x) {
    __shared__ float sm[NLEN];
    const int row = blockIdx.x;
    const int t = threadIdx.x;
    const float* __restrict__ tab = g_tab;

    // Vectorized bit-reversed scatter: thread t owns x[16t .. 16t+16).
    // rev13(16t+e) = rev4(e)<<9 | rev9(t).
    {
        const float4* __restrict__ xr4 =
            reinterpret_cast<const float4*>(x + (size_t)row * NLEN);
        const int rt = rev9(t);
        const int REV4[16] = {0,8,4,12, 2,10,6,14, 1,9,5,13, 3,11,7,15};
        #pragma unroll
        for (int q = 0; q < 4; q++) {
            float4 v = xr4[t * 4 + q];
            sm[swz((REV4[4*q+0] << 9) | rt)] = v.x;
            sm[swz((REV4[4*q+1] << 9) | rt)] = v.y;
            sm[swz((REV4[4*q+2] << 9) | rt)] = v.z;
            sm[swz((REV4[4*q+3] << 9) | rt)] = v.w;
        }
    }
    __syncthreads();

    float r[16];

    // Phase A: stages 1-4 on u = 16t+e (zero table loads)
    {
        #pragma unroll
        for (int e = 0; e < 16; e++) r[e] = sm[swz(t * 16 + e)];
        stagesA(r);
        #pragma unroll
        for (int e = 0; e < 16; e++) sm[swz(t * 16 + e)] = r[e];
    }
    __syncthreads();

    phaseB(sm, r, t, tab);
    __syncthreads();

    // Phase C: stages 9-12, 11/12 pruned (modes<1024). Derived twiddles.
    {
        const int low8 = t & 255;
        const int base = ((t >> 8) << 12) | low8;
        float c9   = tab[low8 << 4];
        float c10p = tab[low8 << 3], c10m = tab[8192 - (low8 << 3)];
        float c11p = tab[low8 << 2], c11m = tab[8192 - (low8 << 2)];
        float c12p = tab[low8 << 1], c12m = tab[8192 - (low8 << 1)];
        #pragma unroll
        for (int s = 0; s < 16; s++) r[s] = sm[swz(base | (s << 8))];
        // stage 9
        #pragma unroll
        for (int s = 0; s < 16; s += 2) {
            float o = c9 * r[s + 1]; r[s + 1] = r[s] - o; r[s] += o;
        }
        // stage 10: sb=0 -> c10p, sb=1 -> cas(th+pi/2) = c10m
        #pragma unroll
        for (int g = 0; g < 16; g += 4) {
            float o0 = c10p * r[g + 2]; r[g + 2] = r[g]     - o0; r[g]     += o0;
            float o1 = c10m * r[g + 3]; r[g + 3] = r[g + 1] - o1; r[g + 1] += o1;
        }
        // stage 11 pruned: '+' branch only
        {
            const float w11[4] = { c11p, RSQ2 * (c11p + c11m), c11m, RSQ2 * (c11m - c11p) };
            #pragma unroll
            for (int sb = 0; sb < 4; sb++) {
                r[sb]     += w11[sb] * r[sb + 4];
                r[sb + 8] += w11[sb] * r[sb + 12];
            }
        }
        // stage 12 pruned: s in 0..3
        {
            r[0] += c12p * r[8];
            r[1] += (C8L * c12p + S8L * c12m) * r[9];
            r[2] += (RSQ2 * (c12p + c12m))    * r[10];
            r[3] += (S8L * c12p + C8L * c12m) * r[11];
        }
        #pragma unroll
        for (int s = 0; s < 4; s++) sm[swz(base | (s << 8))] = r[s];
    }
    __syncthreads();

    // stage 13 pruned + vectorized output: thread t -> modes 2t, 2t+1
    {
        float* __restrict__ xmr = g_xm + (size_t)row * MODES;
        const int m0 = 2 * t;
        float2 tw = *(const float2*)&tab[m0];      // coalesced twiddles
        float e0 = sm[swz(m0)],     o0 = sm[swz(m0 + 4096)];
        float e1 = sm[swz(m0 + 1)], o1 = sm[swz(m0 + 1 + 4096)];
        float2 res;
        res.x = e0 + tw.x * o0;
        res.y = e1 + tw.y * o1;
        *(float2*)&xmr[m0] = res;
    }
}

// -------- inverse: z[row][0..1024) zero-padded -> out[row][0..8192)/8192 ----
__global__ __launch_bounds__(512, 2) void fht_inv_kernel(float* __restrict__ out) {
    __shared__ float sm[NLEN];
    const int row = blockIdx.x;
    const int t = threadIdx.x;
    const float* __restrict__ tab = g_tab;
    const float* __restrict__ zr = g_z + (size_t)row * MODES;

    // stages 1-4 from the two nonzero values; coalesced loads:
    // thread t owns u-block rev9(t)<<4, loads z[t], z[t+512].
    {
        float v0 = zr[t];
        float v1 = zr[t + 512];
        const int ub = rev9(t) << 4;
        const float c4[8] = {1.0f, 1.30656296487637653f, 1.41421356237309515f,
                             1.30656296487637653f, 1.0f, 0.54119610014619701f,
                             0.0f, -0.54119610014619701f};
        #pragma unroll
        for (int e = 0; e < 8; e++) {
            float o = c4[e] * v1;
            sm[swz(ub | e)]       = v0 + o;
            sm[swz(ub | (e + 8))] = v0 - o;
        }
    }
    __syncthreads();

    float r[16];
    phaseB(sm, r, t, tab);
    __syncthreads();

    // Phase C: stages 9-12 full, derived twiddles
    {
        const int low8 = t & 255;
        const int base = ((t >> 8) << 12) | low8;
        float c9   = tab[low8 << 4];
        float c10p = tab[low8 << 3], c10m = tab[8192 - (low8 << 3)];
        float c11p = tab[low8 << 2], c11m = tab[8192 - (low8 << 2)];
        float c12p = tab[low8 << 1], c12m = tab[8192 - (low8 << 1)];
        #pragma unroll
        for (int s = 0; s < 16; s++) r[s] = sm[swz(base | (s << 8))];
        // stage 9
        #pragma unroll
        for (int s = 0; s < 16; s += 2) {
            float o = c9 * r[s + 1]; r[s + 1] = r[s] - o; r[s] += o;
        }
        // stage 10
        #pragma unroll
        for (int g = 0; g < 16; g += 4) {
            float o0 = c10p * r[g + 2]; r[g + 2] = r[g]     - o0; r[g]     += o0;
            float o1 = c10m * r[g + 3]; r[g + 3] = r[g + 1] - o1; r[g + 1] += o1;
        }
        // stage 11 full
        {
            const float w11[4] = { c11p, RSQ2 * (c11p + c11m), c11m, RSQ2 * (c11m - c11p) };
            #pragma unroll
            for (int sb = 0; sb < 4; sb++) {
                float o0 = w11[sb] * r[sb + 4];  r[sb + 4]  = r[sb]     - o0; r[sb]     += o0;
                float o1 = w11[sb] * r[sb + 12]; r[sb + 12] = r[sb + 8] - o1; r[sb + 8] += o1;
            }
        }
        // stage 12 full: cas(th2 + s*pi/8)
        {
            const float w12[8] = {
                c12p,
                C8L * c12p + S8L * c12m,
                RSQ2 * (c12p + c12m),
                S8L * c12p + C8L * c12m,
                c12m,
                -S8L * c12p + C8L * c12m,
                RSQ2 * (c12m - c12p),
                -C8L * c12p + S8L * c12m
            };
            #pragma unroll
            for (int s = 0; s < 8; s++) {
                float o = w12[s] * r[s + 8]; r[s + 8] = r[s] - o; r[s] += o;
            }
        }
        #pragma unroll
        for (int s = 0; s < 16; s++) sm[swz(base | (s << 8))] = r[s];
    }
    __syncthreads();

    // stage 13 + scaled vectorized store: thread t owns k = 8t..8t+8
    {
        const float scale = 1.0f / (float)NLEN;
        float* __restrict__ orow = out + (size_t)row * NLEN;
        const int k0 = 8 * t;
        float4 tw0 = *(const float4*)&tab[k0];       // cas(k0..k0+3)
        float4 tw1 = *(const float4*)&tab[k0 + 4];   // cas(k0+4..k0+7)
        float tws[8] = {tw0.x, tw0.y, tw0.z, tw0.w, tw1.x, tw1.y, tw1.z, tw1.w};
        float lo[8], hi[8];
        #pragma unroll
        for (int q = 0; q < 8; q++) {
            float e = sm[swz(k0 + q)];
            float o = sm[swz(k0 + q + 4096)];
            float tt = tws[q] * o;
            lo[q] = (e + tt) * scale;
            hi[q] = (e - tt) * scale;
        }
        *(float4*)&orow[k0]            = make_float4(lo[0], lo[1], lo[2], lo[3]);
        *(float4*)&orow[k0 + 4]        = make_float4(lo[4], lo[5], lo[6], lo[7]);
        *(float4*)&orow[k0 + 4096]     = make_float4(hi[0], hi[1], hi[2], hi[3]);
        *(float4*)&orow[k0 + 4100]     = make_float4(hi[4], hi[5], hi[6], hi[7]);
    }
}

// -------- generic 32x32 transpose ------------------------------------------
__global__ void transpose_kernel(const float* __restrict__ src,
                                 float* __restrict__ dst, int R, int C) {
    __shared__ float tile[32][33];
    int c0 = blockIdx.x * 32, r0 = blockIdx.y * 32;
    int tx = threadIdx.x, ty = threadIdx.y;
    #pragma unroll
    for (int dy = 0; dy < 32; dy += 8)
        tile[ty + dy][tx] = src[(size_t)(r0 + ty + dy) * C + (c0 + tx)];
    __syncthreads();
    #pragma unroll
    for (int dy = 0; dy < 32; dy += 8)
        dst[(size_t)(c0 + ty + dy) * R + (r0 + tx)] = tile[tx][ty + dy];
}

// -------- paired mode mixing: block m computes z(m) AND z(m') ---------------
__global__ __launch_bounds__(256) void mix_kernel() {
    __shared__ float sa[IROWS];
    __shared__ float sd[IROWS];
    __shared__ float w0[CIN * COUT];
    __shared__ float w1[CIN * COUT];

    const int m  = blockIdx.x;                 // 0..512
    const int mp = (MODES - m) & (MODES - 1);
    const int tid = threadIdx.x;

    const float* xm0 = g_xmT + (size_t)m  * IROWS;
    const float* xm1 = g_xmT + (size_t)mp * IROWS;
    for (int t = tid; t < IROWS; t += 256) {
        float v0 = xm0[t], v1 = xm1[t];
        sa[t] = 0.5f * (v0 + v1);
        sd[t] = 0.5f * (v0 - v1);
    }
    const float* wm0 = g_wT + (size_t)m  * (CIN * COUT);
    const float* wm1 = g_wT + (size_t)mp * (CIN * COUT);
    for (int t = tid; t < CIN * COUT; t += 256) {
        w0[t] = wm0[t];
        w1[t] = wm1[t];
    }
    __syncthreads();

    const int b0 = (tid >> 4) * 2;
    const int o0 = (tid & 15) * 4;

    float A00=0.f,A01=0.f,A02=0.f,A03=0.f, A10=0.f,A11=0.f,A12=0.f,A13=0.f;
    float B00=0.f,B01=0.f,B02=0.f,B03=0.f, B10=0.f,B11=0.f,B12=0.f,B13=0.f;

    #pragma unroll 4
    for (int i = 0; i < CIN; i++) {
        float a0 = sa[b0 * CIN + i];
        float a1 = sa[(b0 + 1) * CIN + i];
        float d0 = sd[b0 * CIN + i];
        float d1 = sd[(b0 + 1) * CIN + i];
        float4 ww0 = *(const float4*)&w0[i * COUT + o0];
        float4 ww1 = *(const float4*)&w1[i * COUT + o0];
        A00 += a0*ww0.x + d0*ww1.x;  A01 += a0*ww0.y + d0*ww1.y;
        A02 += a0*ww0.z + d0*ww1.z;  A03 += a0*ww0.w + d0*ww1.w;
        A10 += a1*ww0.x + d1*ww1.x;  A11 += a1*ww0.y + d1*ww1.y;
        A12 += a1*ww0.z + d1*ww1.z;  A13 += a1*ww0.w + d1*ww1.w;
        B00 += a0*ww1.x - d0*ww0.x;  B01 += a0*ww1.y - d0*ww0.y;
        B02 += a0*ww1.z - d0*ww0.z;  B03 += a0*ww1.w - d0*ww0.w;
        B10 += a1*ww1.x - d1*ww0.x;  B11 += a1*ww1.y - d1*ww0.y;
        B12 += a1*ww1.z - d1*ww0.z;  B13 += a1*ww1.w - d1*ww0.w;
    }

    float* zr = g_zT + (size_t)m * OROWS;
    zr[b0*COUT + o0 + 0] = A00; zr[b0*COUT + o0 + 1] = A01;
    zr[b0*COUT + o0 + 2] = A02; zr[b0*COUT + o0 + 3] = A03;
    zr[(b0+1)*COUT + o0 + 0] = A10; zr[(b0+1)*COUT + o0 + 1] = A11;
    zr[(b0+1)*COUT + o0 + 2] = A12; zr[(b0+1)*COUT + o0 + 3] = A13;

    if (mp != m) {
        float* zp = g_zT + (size_t)mp * OROWS;
        zp[b0*COUT + o0 + 0] = B00; zp[b0*COUT + o0 + 1] = B01;
        zp[b0*COUT + o0 + 2] = B02; zp[b0*COUT + o0 + 3] = B03;
        zp[(b0+1)*COUT + o0 + 0] = B10; zp[(b0+1)*COUT + o0 + 1] = B11;
        zp[(b0+1)*COUT + o0 + 2] = B12; zp[(b0+1)*COUT + o0 + 3] = B13;
    }
}

// ---------------------------------------------------------------------------
extern "C" void kernel_launch(void* const* d_in, const int* in_sizes, int n_in,
                              void* d_out, int out_size) {
    const float* x = (const float*)d_in[0];   // [32][64][8192]
    const float* w = (const float*)d_in[1];   // [64][64][1024]
    float* out = (float*)d_out;               // [32][64][8192]

    float* xm  = nullptr; cudaGetSymbolAddress((void**)&xm,  g_xm);
    float* xmT = nullptr; cudaGetSymbolAddress((void**)&xmT, g_xmT);
    float* wT  = nullptr; cudaGetSymbolAddress((void**)&wT,  g_wT);
    float* zT  = nullptr; cudaGetSymbolAddress((void**)&zT,  g_zT);
    float* z   = nullptr; cudaGetSymbolAddress((void**)&z,   g_z);

    init_table_kernel<<<(NLEN + 512) / 512, 512>>>();

    fht_fwd_kernel<<<IROWS, 512>>>(x);

    // xm [2048][1024] -> xmT [1024][2048]
    transpose_kernel<<<dim3(MODES / 32, IROWS / 32), dim3(32, 8)>>>(xm, xmT, IROWS, MODES);
    // w  [4096][1024] -> wT  [1024][4096]
    transpose_kernel<<<dim3(MODES / 32, (CIN * COUT) / 32), dim3(32, 8)>>>(w, wT, CIN * COUT, MODES);

    mix_kernel<<<MODES / 2 + 1, 256>>>();     // 513 blocks: m and m' paired

    // zT [1024][2048] -> z [2048][1024]
    transpose_kernel<<<dim3(OROWS / 32, MODES / 32), dim3(32, 8)>>>(zT, z, MODES, OROWS);

    fht_inv_kernel<<<OROWS, 512>>>(out);
}